// round 1
// baseline (speedup 1.0000x reference)
#include <cuda_runtime.h>
#include <cfloat>
#include <cstdint>

// Problem constants
#define BB   4
#define NPTS 4096
#define KNN  16
#define DP   128
#define DM   256
#define TOT  (BB*NPTS)   // 16384

// ---------------- scratch (static device globals; no allocation) ------------
__device__ __align__(64) float g_x[(size_t)TOT*DM];          // 16 MB
__device__ __align__(64) float g_qkvg[(size_t)TOT*1024];     // 64 MB: [q|k|v|g]
__device__ __align__(64) float g_svA[(size_t)TOT*512];       // 32 MB: [sv|A]
__device__ __align__(64) int   g_knn[(size_t)TOT*KNN];
__device__ __align__(64) float g_Wbig[256*1024];             // [wq|wk|wv|wq@fd2^T]
__device__ __align__(64) float g_W2[512*128];                // [fc2 ; fd2@fc2]
__device__ __align__(64) float g_cvec[128];                  // fd2_b@fc2 + fc2_b

// ---------------- prep kernels ----------------------------------------------
__global__ void prep_wbig_k(const float* __restrict__ wq, const float* __restrict__ wk,
                            const float* __restrict__ wv, const float* __restrict__ fd2,
                            float* __restrict__ Wbig)
{
    int idx = blockIdx.x * blockDim.x + threadIdx.x;   // 256*1024 threads
    int r = idx >> 10, c = idx & 1023;
    float v;
    if (c < 256)       v = wq[r*256 + c];
    else if (c < 512)  v = wk[r*256 + (c-256)];
    else if (c < 768)  v = wv[r*256 + (c-512)];
    else {
        int j = c - 768;
        float s = 0.f;
        for (int d = 0; d < 256; ++d) s += wq[r*256 + d] * fd2[j*256 + d];
        v = s;
    }
    Wbig[idx] = v;
}

__global__ void prep_w2_k(const float* __restrict__ fc2, const float* __restrict__ fd2,
                          const float* __restrict__ fd2b, const float* __restrict__ fc2b,
                          float* __restrict__ W2, float* __restrict__ cvec)
{
    int idx = blockIdx.x * blockDim.x + threadIdx.x;   // 512*128 threads
    if (idx < 512*128) {
        int r = idx >> 7, c = idx & 127;
        float v;
        if (r < 256) v = fc2[idx];
        else {
            int rr = r - 256;
            float s = 0.f;
            for (int d = 0; d < 256; ++d) s += fd2[rr*256 + d] * fc2[d*128 + c];
            v = s;
        }
        W2[idx] = v;
    }
    if (idx < 128) {
        float s = fc2b[idx];
        for (int d = 0; d < 256; ++d) s += fd2b[d] * fc2[d*128 + idx];
        cvec[idx] = s;
    }
}

// ---------------- KNN: brute force in shared memory -------------------------
// grid (128, B), block 256, dyn smem 64KB. 1 warp per query, lane-strided scan,
// per-lane top-16 (max-replace), warp merge (16 rounds of lexicographic min).
__global__ __launch_bounds__(256)
void knn_kernel(const float* __restrict__ xyz, int* __restrict__ knn)
{
    extern __shared__ float sh[];
    float* sx = sh;
    float* sy = sh + NPTS;
    float* sz = sh + 2*NPTS;
    float* sq = sh + 3*NPTS;
    const int b = blockIdx.y;
    const float* xb = xyz + (size_t)b * NPTS * 3;
    for (int p = threadIdx.x; p < NPTS; p += blockDim.x) {
        float x = xb[3*p], y = xb[3*p+1], z = xb[3*p+2];
        sx[p] = x; sy[p] = y; sz[p] = z;
        sq[p] = x*x + y*y + z*z;
    }
    __syncthreads();

    const int warp = threadIdx.x >> 5, lane = threadIdx.x & 31;
    const int QPB = 32;
    for (int qi = warp; qi < QPB; qi += 8) {
        const int qn = blockIdx.x * QPB + qi;
        const float qx = sx[qn], qy = sy[qn], qz = sz[qn], qs = sq[qn];

        float bd[16]; int bi[16];
        #pragma unroll
        for (int j = 0; j < 16; ++j) { bd[j] = FLT_MAX; bi[j] = 0x7fffffff; }
        float wd = FLT_MAX; int wid = 0x7fffffff; int ws = 0;

        for (int c = lane; c < NPTS; c += 32) {
            float dot = qx*sx[c] + qy*sy[c] + qz*sz[c];
            float d = (qs + sq[c]) - 2.0f * dot;
            if (d < wd || (d == wd && c < wid)) {
                bd[ws] = d; bi[ws] = c;
                // recompute worst (lexicographic max)
                wd = -FLT_MAX; wid = -1; ws = 0;
                #pragma unroll
                for (int j = 0; j < 16; ++j) {
                    if (bd[j] > wd || (bd[j] == wd && bi[j] > wid)) {
                        wd = bd[j]; wid = bi[j]; ws = j;
                    }
                }
            }
        }

        // local min state
        float md = FLT_MAX; int mi = 0x7fffffff; int ms = 0;
        #pragma unroll
        for (int j = 0; j < 16; ++j) {
            if (bd[j] < md || (bd[j] == md && bi[j] < mi)) { md = bd[j]; mi = bi[j]; ms = j; }
        }

        int* outrow = knn + ((size_t)(b*NPTS + qn)) * KNN;
        #pragma unroll
        for (int r = 0; r < KNN; ++r) {
            float rd = md; int ri = mi;
            #pragma unroll
            for (int off = 16; off; off >>= 1) {
                float od = __shfl_xor_sync(0xffffffffu, rd, off);
                int   oi = __shfl_xor_sync(0xffffffffu, ri, off);
                if (od < rd || (od == rd && oi < ri)) { rd = od; ri = oi; }
            }
            if (lane == 0) outrow[r] = ri;
            if (ri == mi && rd == md) {
                // my entry won; consume and recompute local min
                bd[ms] = FLT_MAX; bi[ms] = 0x7fffffff;
                md = FLT_MAX; mi = 0x7fffffff; ms = 0;
                #pragma unroll
                for (int j = 0; j < 16; ++j) {
                    if (bd[j] < md || (bd[j] == md && bi[j] < mi)) { md = bd[j]; mi = bi[j]; ms = j; }
                }
            }
        }
    }
}

// ---------------- fp32 SGEMM: 128x128 tile, 8x8/thread ----------------------
// A [M,K] row-major, B [K,N] row-major, C [M,N] row-major.
// EPI=0: C = A@B + bias (bias optional)
// EPI=1: (N==128) val = A@B + bias + resid[m,:]; transpose-store to outT[b,c,nn]
template <int EPI>
__global__ __launch_bounds__(256)
void sgemm_k(const float* __restrict__ A, const float* __restrict__ Bm,
             const float* __restrict__ bias, float* __restrict__ C,
             int M, int N, int K,
             const float* __restrict__ resid, float* __restrict__ outT)
{
    __shared__ float As[16][132];
    __shared__ float Bs[16][128];
    const int tid = threadIdx.x;
    const int tx = tid & 15, ty = tid >> 4;
    const int bm = blockIdx.y * 128, bn = blockIdx.x * 128;

    const int ar0 = tid >> 2, ac = (tid & 3) << 2;
    const int br0 = tid >> 5, bc = (tid & 31) << 2;

    float acc[8][8];
    #pragma unroll
    for (int i = 0; i < 8; ++i)
        #pragma unroll
        for (int j = 0; j < 8; ++j) acc[i][j] = 0.f;

    const float* Ap0 = A + (size_t)(bm + ar0) * K + ac;
    const float* Ap1 = Ap0 + (size_t)64 * K;
    const float* Bp0 = Bm + (size_t)br0 * N + bn + bc;
    const float* Bp1 = Bp0 + (size_t)8 * N;

    for (int k0 = 0; k0 < K; k0 += 16) {
        float4 av0 = *(const float4*)(Ap0 + k0);
        float4 av1 = *(const float4*)(Ap1 + k0);
        float4 bv0 = *(const float4*)(Bp0 + (size_t)k0 * N);
        float4 bv1 = *(const float4*)(Bp1 + (size_t)k0 * N);
        __syncthreads();
        As[ac+0][ar0] = av0.x; As[ac+1][ar0] = av0.y; As[ac+2][ar0] = av0.z; As[ac+3][ar0] = av0.w;
        As[ac+0][ar0+64] = av1.x; As[ac+1][ar0+64] = av1.y; As[ac+2][ar0+64] = av1.z; As[ac+3][ar0+64] = av1.w;
        *(float4*)&Bs[br0][bc] = bv0;
        *(float4*)&Bs[br0+8][bc] = bv1;
        __syncthreads();
        #pragma unroll
        for (int kk = 0; kk < 16; ++kk) {
            float4 a0 = *(const float4*)&As[kk][ty << 2];
            float4 a1 = *(const float4*)&As[kk][(ty << 2) + 64];
            float4 b0 = *(const float4*)&Bs[kk][tx << 2];
            float4 b1 = *(const float4*)&Bs[kk][(tx << 2) + 64];
            float a[8] = {a0.x,a0.y,a0.z,a0.w, a1.x,a1.y,a1.z,a1.w};
            float bvals[8] = {b0.x,b0.y,b0.z,b0.w, b1.x,b1.y,b1.z,b1.w};
            #pragma unroll
            for (int i = 0; i < 8; ++i)
                #pragma unroll
                for (int j = 0; j < 8; ++j)
                    acc[i][j] = fmaf(a[i], bvals[j], acc[i][j]);
        }
    }

    float4 bb0 = make_float4(0.f,0.f,0.f,0.f), bb1 = bb0;
    if (bias) {
        bb0 = *(const float4*)(bias + bn + (tx << 2));
        bb1 = *(const float4*)(bias + bn + (tx << 2) + 64);
    }

    if (EPI == 0) {
        #pragma unroll
        for (int i = 0; i < 8; ++i) {
            int r = bm + (ty << 2) + (i & 3) + ((i & 4) << 4);
            float4 o0 = make_float4(acc[i][0]+bb0.x, acc[i][1]+bb0.y, acc[i][2]+bb0.z, acc[i][3]+bb0.w);
            float4 o1 = make_float4(acc[i][4]+bb1.x, acc[i][5]+bb1.y, acc[i][6]+bb1.z, acc[i][7]+bb1.w);
            *(float4*)(C + (size_t)r * N + bn + (tx << 2)) = o0;
            *(float4*)(C + (size_t)r * N + bn + (tx << 2) + 64) = o1;
        }
    } else {
        float barr[8] = {bb0.x,bb0.y,bb0.z,bb0.w, bb1.x,bb1.y,bb1.z,bb1.w};
        #pragma unroll
        for (int i = 0; i < 8; ++i) {
            int r = bm + (ty << 2) + (i & 3) + ((i & 4) << 4);   // global point index
            int bidx = r >> 12;
            int nn = r & 4095;
            const float* frow = resid + (size_t)r * 128;
            float* obase = outT + ((size_t)bidx << 19) + nn;     // b*128*4096 + nn
            #pragma unroll
            for (int j = 0; j < 8; ++j) {
                int c = (tx << 2) + (j & 3) + ((j & 4) << 4);
                obase[(size_t)c << 12] = acc[i][j] + barr[j] + frow[c];
            }
        }
    }
}

// ---------------- fused neighborhood attention -------------------------------
// 1 warp per point. Pass1: logits = (q.kf + h.g)/16 with h = relu(delta@fd1+b1).
// Softmax over 16. Pass2: sv = sum attn*vf, A = sum attn*h (h recomputed).
__global__ __launch_bounds__(128)
void attn_k(const float* __restrict__ qkvg, const float* __restrict__ xyz,
            const int* __restrict__ knn, const float* __restrict__ fd1w,
            const float* __restrict__ fd1b, float* __restrict__ svA)
{
    __shared__ float sw[768];
    __shared__ float sb[256];
    const int tid = threadIdx.x;
    for (int i = tid; i < 768; i += 128) sw[i] = fd1w[i];
    for (int i = tid; i < 256; i += 128) sb[i] = fd1b[i];
    __syncthreads();

    const int lane = tid & 31, warp = tid >> 5;
    const int n = blockIdx.x * 4 + warp;       // global point, 16384
    const int gbase = n & ~(NPTS - 1);         // b*4096

    const float4* qv = (const float4*)(qkvg + (size_t)n * 1024);
    const float4 q0 = qv[lane],       q1 = qv[32 + lane];
    const float4 gg0 = qv[192 + lane], gg1 = qv[224 + lane];

    const int c0 = lane << 2;
    const float4 w00 = *(const float4*)(sw + c0);
    const float4 w01 = *(const float4*)(sw + 256 + c0);
    const float4 w02 = *(const float4*)(sw + 512 + c0);
    const float4 b0v = *(const float4*)(sb + c0);
    const float4 w10 = *(const float4*)(sw + c0 + 128);
    const float4 w11 = *(const float4*)(sw + 256 + c0 + 128);
    const float4 w12 = *(const float4*)(sw + 512 + c0 + 128);
    const float4 b1v = *(const float4*)(sb + c0 + 128);

    const float px = xyz[(size_t)n*3], py = xyz[(size_t)n*3+1], pz = xyz[(size_t)n*3+2];
    int myidx = 0; float mdx = 0.f, mdy = 0.f, mdz = 0.f;
    if (lane < 16) {
        myidx = knn[(size_t)n * KNN + lane];
        const float* nb = xyz + (size_t)(gbase + myidx) * 3;
        mdx = px - nb[0]; mdy = py - nb[1]; mdz = pz - nb[2];
    }

    float l[16];
    #pragma unroll
    for (int k = 0; k < 16; ++k) {
        const int idx = __shfl_sync(0xffffffffu, myidx, k);
        const float dx = __shfl_sync(0xffffffffu, mdx, k);
        const float dy = __shfl_sync(0xffffffffu, mdy, k);
        const float dz = __shfl_sync(0xffffffffu, mdz, k);
        const float4* kv = (const float4*)(qkvg + (size_t)(gbase + idx) * 1024);
        const float4 kk0 = kv[64 + lane], kk1 = kv[96 + lane];
        float4 h0, h1;
        h0.x = fmaxf(0.f, dx*w00.x + dy*w01.x + dz*w02.x + b0v.x);
        h0.y = fmaxf(0.f, dx*w00.y + dy*w01.y + dz*w02.y + b0v.y);
        h0.z = fmaxf(0.f, dx*w00.z + dy*w01.z + dz*w02.z + b0v.z);
        h0.w = fmaxf(0.f, dx*w00.w + dy*w01.w + dz*w02.w + b0v.w);
        h1.x = fmaxf(0.f, dx*w10.x + dy*w11.x + dz*w12.x + b1v.x);
        h1.y = fmaxf(0.f, dx*w10.y + dy*w11.y + dz*w12.y + b1v.y);
        h1.z = fmaxf(0.f, dx*w10.z + dy*w11.z + dz*w12.z + b1v.z);
        h1.w = fmaxf(0.f, dx*w10.w + dy*w11.w + dz*w12.w + b1v.w);
        float p = q0.x*kk0.x + q0.y*kk0.y + q0.z*kk0.z + q0.w*kk0.w
                + q1.x*kk1.x + q1.y*kk1.y + q1.z*kk1.z + q1.w*kk1.w
                + h0.x*gg0.x + h0.y*gg0.y + h0.z*gg0.z + h0.w*gg0.w
                + h1.x*gg1.x + h1.y*gg1.y + h1.z*gg1.z + h1.w*gg1.w;
        #pragma unroll
        for (int off = 16; off; off >>= 1) p += __shfl_xor_sync(0xffffffffu, p, off);
        l[k] = p * 0.0625f;
    }

    float mx = l[0];
    #pragma unroll
    for (int k = 1; k < 16; ++k) mx = fmaxf(mx, l[k]);
    float s = 0.f;
    #pragma unroll
    for (int k = 0; k < 16; ++k) { l[k] = __expf(l[k] - mx); s += l[k]; }
    const float inv = 1.f / s;

    float4 sv0 = make_float4(0,0,0,0), sv1 = sv0, A0 = sv0, A1 = sv0;
    #pragma unroll
    for (int k = 0; k < 16; ++k) {
        const float a = l[k] * inv;
        const int idx = __shfl_sync(0xffffffffu, myidx, k);
        const float dx = __shfl_sync(0xffffffffu, mdx, k);
        const float dy = __shfl_sync(0xffffffffu, mdy, k);
        const float dz = __shfl_sync(0xffffffffu, mdz, k);
        const float4* kv = (const float4*)(qkvg + (size_t)(gbase + idx) * 1024);
        const float4 v0 = kv[128 + lane], v1 = kv[160 + lane];
        float4 h0, h1;
        h0.x = fmaxf(0.f, dx*w00.x + dy*w01.x + dz*w02.x + b0v.x);
        h0.y = fmaxf(0.f, dx*w00.y + dy*w01.y + dz*w02.y + b0v.y);
        h0.z = fmaxf(0.f, dx*w00.z + dy*w01.z + dz*w02.z + b0v.z);
        h0.w = fmaxf(0.f, dx*w00.w + dy*w01.w + dz*w02.w + b0v.w);
        h1.x = fmaxf(0.f, dx*w10.x + dy*w11.x + dz*w12.x + b1v.x);
        h1.y = fmaxf(0.f, dx*w10.y + dy*w11.y + dz*w12.y + b1v.y);
        h1.z = fmaxf(0.f, dx*w10.z + dy*w11.z + dz*w12.z + b1v.z);
        h1.w = fmaxf(0.f, dx*w10.w + dy*w11.w + dz*w12.w + b1v.w);
        sv0.x += a*v0.x; sv0.y += a*v0.y; sv0.z += a*v0.z; sv0.w += a*v0.w;
        sv1.x += a*v1.x; sv1.y += a*v1.y; sv1.z += a*v1.z; sv1.w += a*v1.w;
        A0.x += a*h0.x; A0.y += a*h0.y; A0.z += a*h0.z; A0.w += a*h0.w;
        A1.x += a*h1.x; A1.y += a*h1.y; A1.z += a*h1.z; A1.w += a*h1.w;
    }

    float4* o = (float4*)(svA + (size_t)n * 512);
    o[lane] = sv0; o[32 + lane] = sv1; o[64 + lane] = A0; o[96 + lane] = A1;
}

// ---------------- launch -----------------------------------------------------
extern "C" void kernel_launch(void* const* d_in, const int* in_sizes, int n_in,
                              void* d_out, int out_size)
{
    const float* features = (const float*)d_in[0];
    const float* xyz      = (const float*)d_in[1];
    const float* fc1w     = (const float*)d_in[2];
    const float* fc1b     = (const float*)d_in[3];
    const float* fc2w     = (const float*)d_in[4];
    const float* fc2b     = (const float*)d_in[5];
    const float* fd1w     = (const float*)d_in[6];
    const float* fd1b     = (const float*)d_in[7];
    const float* fd2w     = (const float*)d_in[8];
    const float* fd2b     = (const float*)d_in[9];
    const float* wq       = (const float*)d_in[10];
    const float* wk       = (const float*)d_in[11];
    const float* wv       = (const float*)d_in[12];
    float* out = (float*)d_out;

    void *p_x, *p_qkvg, *p_svA, *p_knn, *p_Wbig, *p_W2, *p_cvec;
    cudaGetSymbolAddress(&p_x, g_x);
    cudaGetSymbolAddress(&p_qkvg, g_qkvg);
    cudaGetSymbolAddress(&p_svA, g_svA);
    cudaGetSymbolAddress(&p_knn, g_knn);
    cudaGetSymbolAddress(&p_Wbig, g_Wbig);
    cudaGetSymbolAddress(&p_W2, g_W2);
    cudaGetSymbolAddress(&p_cvec, g_cvec);

    // prep folded weights
    prep_wbig_k<<<1024, 256>>>(wq, wk, wv, fd2w, (float*)p_Wbig);
    prep_w2_k<<<256, 256>>>(fc2w, fd2w, fd2b, fc2b, (float*)p_W2, (float*)p_cvec);

    // KNN
    cudaFuncSetAttribute((const void*)knn_kernel,
                         cudaFuncAttributeMaxDynamicSharedMemorySize, 65536);
    knn_kernel<<<dim3(128, BB), 256, 65536>>>(xyz, (int*)p_knn);

    // x = features @ fc1 + b1
    sgemm_k<0><<<dim3(2, 128), 256>>>(features, fc1w, fc1b, (float*)p_x,
                                      TOT, 256, 128, nullptr, nullptr);
    // [q|k|v|g] = x @ Wbig
    sgemm_k<0><<<dim3(8, 128), 256>>>((const float*)p_x, (const float*)p_Wbig, nullptr,
                                      (float*)p_qkvg, TOT, 1024, 256, nullptr, nullptr);
    // attention -> [sv|A]
    attn_k<<<4096, 128>>>((const float*)p_qkvg, xyz, (const int*)p_knn,
                          fd1w, fd1b, (float*)p_svA);
    // out = [sv|A] @ [fc2; fd2@fc2] + cvec + features, transposed store
    sgemm_k<1><<<dim3(1, 128), 256>>>((const float*)p_svA, (const float*)p_W2,
                                      (const float*)p_cvec, nullptr,
                                      TOT, 128, 512, features, out);
}

// round 2
// speedup vs baseline: 1.2828x; 1.2828x over previous
#include <cuda_runtime.h>
#include <cfloat>
#include <cstdint>

// Problem constants
#define BB   4
#define NPTS 4096
#define KNN  16
#define DP   128
#define DM   256
#define TOT  (BB*NPTS)   // 16384

// ---------------- scratch (static device globals; no allocation) ------------
__device__ __align__(64) float g_qkvg[(size_t)TOT*1024];     // 64 MB: [q|k|v|g]
__device__ __align__(64) float g_svA[(size_t)TOT*512];       // 32 MB: [sv|A]
__device__ __align__(64) int   g_knn[(size_t)TOT*KNN];
__device__ __align__(64) float g_Wbig[256*1024];             // [wq|wk|wv|wq@fd2^T]
__device__ __align__(64) float g_W1big[128*1024];            // fc1 @ Wbig
__device__ __align__(64) float g_bvec[1024];                 // fc1_b @ Wbig
__device__ __align__(64) float g_W2[512*128];                // [fc2 ; fd2@fc2]
__device__ __align__(64) float g_cvec[128];                  // fd2_b@fc2 + fc2_b
__device__ __align__(64) float g_fd2T[256*256];
__device__ __align__(64) float g_G[256*256];                 // wq @ fd2^T

// ---------------- prep kernels ----------------------------------------------
__global__ void transpose256_k(const float* __restrict__ in, float* __restrict__ out)
{
    __shared__ float tile[32][33];
    int x = blockIdx.x * 32 + threadIdx.x;
    int y = blockIdx.y * 32 + threadIdx.y;
    #pragma unroll
    for (int i = 0; i < 4; ++i)
        tile[threadIdx.y + 8*i][threadIdx.x] = in[(y + 8*i) * 256 + x];
    __syncthreads();
    x = blockIdx.y * 32 + threadIdx.x;
    y = blockIdx.x * 32 + threadIdx.y;
    #pragma unroll
    for (int i = 0; i < 4; ++i)
        out[(y + 8*i) * 256 + x] = tile[threadIdx.x][threadIdx.y + 8*i];
}

__global__ void pack_wbig_k(const float* __restrict__ wq, const float* __restrict__ wk,
                            const float* __restrict__ wv, const float* __restrict__ G,
                            float* __restrict__ Wbig)
{
    int idx = blockIdx.x * blockDim.x + threadIdx.x;   // 256*1024
    int r = idx >> 10, c = idx & 1023;
    float v;
    if (c < 256)       v = wq[r*256 + c];
    else if (c < 512)  v = wk[r*256 + (c-256)];
    else if (c < 768)  v = wv[r*256 + (c-512)];
    else               v = G[r*256 + (c-768)];
    Wbig[idx] = v;
}

__global__ void bvec_k(const float* __restrict__ b1, const float* __restrict__ Wbig,
                       float* __restrict__ bvec)
{
    int j = blockIdx.x * blockDim.x + threadIdx.x;   // 1024
    float s = 0.f;
    for (int d = 0; d < 128; ++d) s += b1[d] * Wbig[d*1024 + j];
    bvec[j] = s;
}

__global__ void prep_w2_k(const float* __restrict__ fc2, const float* __restrict__ fd2,
                          const float* __restrict__ fd2b, const float* __restrict__ fc2b,
                          float* __restrict__ W2, float* __restrict__ cvec)
{
    int idx = blockIdx.x * blockDim.x + threadIdx.x;   // 512*128 threads
    if (idx < 512*128) {
        int r = idx >> 7, c = idx & 127;
        float v;
        if (r < 256) v = fc2[idx];
        else {
            int rr = r - 256;
            float s = 0.f;
            for (int d = 0; d < 256; ++d) s += fd2[rr*256 + d] * fc2[d*128 + c];
            v = s;
        }
        W2[idx] = v;
    }
    if (idx < 128) {
        float s = fc2b[idx];
        for (int d = 0; d < 256; ++d) s += fd2b[d] * fc2[d*128 + idx];
        cvec[idx] = s;
    }
}

// ---------------- KNN: brute force, register-sorted top-16 ------------------
// grid (128, B), block 256, dyn smem 64KB. 1 warp per query, lane-strided scan.
// Each lane keeps an ASCENDING sorted top-16 in registers (static indexing only:
// unrolled compare-swap sift on insert, unrolled shift on extraction).
__device__ __forceinline__ bool knn_better(float d, int i, float d2, int i2)
{
    return d < d2 || (d == d2 && i < i2);
}

__global__ __launch_bounds__(256)
void knn_kernel(const float* __restrict__ xyz, int* __restrict__ knn)
{
    extern __shared__ float sh[];
    float* sx = sh;
    float* sy = sh + NPTS;
    float* sz = sh + 2*NPTS;
    float* sq = sh + 3*NPTS;
    const int b = blockIdx.y;
    const float* xb = xyz + (size_t)b * NPTS * 3;
    for (int p = threadIdx.x; p < NPTS; p += blockDim.x) {
        float x = xb[3*p], y = xb[3*p+1], z = xb[3*p+2];
        sx[p] = x; sy[p] = y; sz[p] = z;
        sq[p] = x*x + y*y + z*z;
    }
    __syncthreads();

    const int warp = threadIdx.x >> 5, lane = threadIdx.x & 31;
    const int QPB = 32;
    for (int qi = warp; qi < QPB; qi += 8) {
        const int qn = blockIdx.x * QPB + qi;
        const float qx = sx[qn], qy = sy[qn], qz = sz[qn], qs = sq[qn];

        float t[16]; int ti[16];
        #pragma unroll
        for (int j = 0; j < 16; ++j) { t[j] = FLT_MAX; ti[j] = 0x7fffffff; }

        for (int c = lane; c < NPTS; c += 32) {
            float dot = qx*sx[c] + qy*sy[c] + qz*sz[c];
            float d = (qs + sq[c]) - 2.0f * dot;
            if (knn_better(d, c, t[15], ti[15])) {
                t[15] = d; ti[15] = c;
                #pragma unroll
                for (int j = 14; j >= 0; --j) {
                    if (knn_better(t[j+1], ti[j+1], t[j], ti[j])) {
                        float td = t[j]; t[j] = t[j+1]; t[j+1] = td;
                        int   tt = ti[j]; ti[j] = ti[j+1]; ti[j+1] = tt;
                    }
                }
            }
        }

        int* outrow = knn + ((size_t)(b*NPTS + qn)) * KNN;
        #pragma unroll
        for (int r = 0; r < KNN; ++r) {
            float rd = t[0]; int ri = ti[0];
            #pragma unroll
            for (int off = 16; off; off >>= 1) {
                float od = __shfl_xor_sync(0xffffffffu, rd, off);
                int   oi = __shfl_xor_sync(0xffffffffu, ri, off);
                if (knn_better(od, oi, rd, ri)) { rd = od; ri = oi; }
            }
            if (lane == 0) outrow[r] = ri;
            if (ti[0] == ri) {   // this lane won: consume head, shift up
                #pragma unroll
                for (int j = 0; j < 15; ++j) { t[j] = t[j+1]; ti[j] = ti[j+1]; }
                t[15] = FLT_MAX; ti[15] = 0x7fffffff;
            }
        }
    }
}

// ---------------- fp32 SGEMM: 128x128 tile, 8x8/thread ----------------------
// A [M,K] row-major, B [K,N] row-major, C [M,N] row-major.
// EPI=0: C = A@B + bias (bias optional)
// EPI=1: (N==128) val = A@B + bias + resid[m,:]; transpose-store to outT[b,c,nn]
template <int EPI>
__global__ __launch_bounds__(256)
void sgemm_k(const float* __restrict__ A, const float* __restrict__ Bm,
             const float* __restrict__ bias, float* __restrict__ C,
             int M, int N, int K,
             const float* __restrict__ resid, float* __restrict__ outT)
{
    __shared__ float As[16][132];
    __shared__ float Bs[16][128];
    const int tid = threadIdx.x;
    const int tx = tid & 15, ty = tid >> 4;
    const int bm = blockIdx.y * 128, bn = blockIdx.x * 128;

    const int ar0 = tid >> 2, ac = (tid & 3) << 2;
    const int br0 = tid >> 5, bc = (tid & 31) << 2;

    float acc[8][8];
    #pragma unroll
    for (int i = 0; i < 8; ++i)
        #pragma unroll
        for (int j = 0; j < 8; ++j) acc[i][j] = 0.f;

    const float* Ap0 = A + (size_t)(bm + ar0) * K + ac;
    const float* Ap1 = Ap0 + (size_t)64 * K;
    const float* Bp0 = Bm + (size_t)br0 * N + bn + bc;
    const float* Bp1 = Bp0 + (size_t)8 * N;

    for (int k0 = 0; k0 < K; k0 += 16) {
        float4 av0 = *(const float4*)(Ap0 + k0);
        float4 av1 = *(const float4*)(Ap1 + k0);
        float4 bv0 = *(const float4*)(Bp0 + (size_t)k0 * N);
        float4 bv1 = *(const float4*)(Bp1 + (size_t)k0 * N);
        __syncthreads();
        As[ac+0][ar0] = av0.x; As[ac+1][ar0] = av0.y; As[ac+2][ar0] = av0.z; As[ac+3][ar0] = av0.w;
        As[ac+0][ar0+64] = av1.x; As[ac+1][ar0+64] = av1.y; As[ac+2][ar0+64] = av1.z; As[ac+3][ar0+64] = av1.w;
        *(float4*)&Bs[br0][bc] = bv0;
        *(float4*)&Bs[br0+8][bc] = bv1;
        __syncthreads();
        #pragma unroll
        for (int kk = 0; kk < 16; ++kk) {
            float4 a0 = *(const float4*)&As[kk][ty << 2];
            float4 a1 = *(const float4*)&As[kk][(ty << 2) + 64];
            float4 b0 = *(const float4*)&Bs[kk][tx << 2];
            float4 b1 = *(const float4*)&Bs[kk][(tx << 2) + 64];
            float a[8] = {a0.x,a0.y,a0.z,a0.w, a1.x,a1.y,a1.z,a1.w};
            float bvals[8] = {b0.x,b0.y,b0.z,b0.w, b1.x,b1.y,b1.z,b1.w};
            #pragma unroll
            for (int i = 0; i < 8; ++i)
                #pragma unroll
                for (int j = 0; j < 8; ++j)
                    acc[i][j] = fmaf(a[i], bvals[j], acc[i][j]);
        }
    }

    float4 bb0 = make_float4(0.f,0.f,0.f,0.f), bb1 = bb0;
    if (bias) {
        bb0 = *(const float4*)(bias + bn + (tx << 2));
        bb1 = *(const float4*)(bias + bn + (tx << 2) + 64);
    }

    if (EPI == 0) {
        #pragma unroll
        for (int i = 0; i < 8; ++i) {
            int r = bm + (ty << 2) + (i & 3) + ((i & 4) << 4);
            float4 o0 = make_float4(acc[i][0]+bb0.x, acc[i][1]+bb0.y, acc[i][2]+bb0.z, acc[i][3]+bb0.w);
            float4 o1 = make_float4(acc[i][4]+bb1.x, acc[i][5]+bb1.y, acc[i][6]+bb1.z, acc[i][7]+bb1.w);
            *(float4*)(C + (size_t)r * N + bn + (tx << 2)) = o0;
            *(float4*)(C + (size_t)r * N + bn + (tx << 2) + 64) = o1;
        }
    } else {
        float barr[8] = {bb0.x,bb0.y,bb0.z,bb0.w, bb1.x,bb1.y,bb1.z,bb1.w};
        #pragma unroll
        for (int i = 0; i < 8; ++i) {
            int r = bm + (ty << 2) + (i & 3) + ((i & 4) << 4);   // global point index
            int bidx = r >> 12;
            int nn = r & 4095;
            const float* frow = resid + (size_t)r * 128;
            float* obase = outT + ((size_t)bidx << 19) + nn;     // b*128*4096 + nn
            #pragma unroll
            for (int j = 0; j < 8; ++j) {
                int c = (tx << 2) + (j & 3) + ((j & 4) << 4);
                obase[(size_t)c << 12] = acc[i][j] + barr[j] + frow[c];
            }
        }
    }
}

// ---------------- fused neighborhood attention (single pass) ----------------
// 1 warp per point, 8 warps/block. Online softmax:
// per k: h = relu(delta@fd1+b1); p = (q.kf + h.g)/16; update (m,s), rescale
// accumulators; sv += a*vf, A += a*h. Final scale by 1/s.
__global__ __launch_bounds__(256)
void attn_k(const float* __restrict__ qkvg, const float* __restrict__ xyz,
            const int* __restrict__ knn, const float* __restrict__ fd1w,
            const float* __restrict__ fd1b, float* __restrict__ svA)
{
    __shared__ float sw[768];
    __shared__ float sb[256];
    const int tid = threadIdx.x;
    for (int i = tid; i < 768; i += 256) sw[i] = fd1w[i];
    for (int i = tid; i < 256; i += 256) sb[i] = fd1b[i];
    __syncthreads();

    const int lane = tid & 31, warp = tid >> 5;
    const int n = blockIdx.x * 8 + warp;       // global point, 16384
    const int gbase = n & ~(NPTS - 1);         // b*4096

    const float4* qv = (const float4*)(qkvg + (size_t)n * 1024);
    const float4 q0 = qv[lane],        q1 = qv[32 + lane];
    const float4 gg0 = qv[192 + lane], gg1 = qv[224 + lane];

    const int c0 = lane << 2;
    const float4 w00 = *(const float4*)(sw + c0);
    const float4 w01 = *(const float4*)(sw + 256 + c0);
    const float4 w02 = *(const float4*)(sw + 512 + c0);
    const float4 b0v = *(const float4*)(sb + c0);
    const float4 w10 = *(const float4*)(sw + c0 + 128);
    const float4 w11 = *(const float4*)(sw + 256 + c0 + 128);
    const float4 w12 = *(const float4*)(sw + 512 + c0 + 128);
    const float4 b1v = *(const float4*)(sb + c0 + 128);

    const float px = xyz[(size_t)n*3], py = xyz[(size_t)n*3+1], pz = xyz[(size_t)n*3+2];
    int myidx = 0; float mdx = 0.f, mdy = 0.f, mdz = 0.f;
    if (lane < 16) {
        myidx = knn[(size_t)n * KNN + lane];
        const float* nb = xyz + (size_t)(gbase + myidx) * 3;
        mdx = px - nb[0]; mdy = py - nb[1]; mdz = pz - nb[2];
    }

    float m = -FLT_MAX, s = 0.f;
    float4 sv0 = make_float4(0,0,0,0), sv1 = sv0, A0 = sv0, A1 = sv0;

    #pragma unroll
    for (int k = 0; k < 16; ++k) {
        const int idx = __shfl_sync(0xffffffffu, myidx, k);
        const float dx = __shfl_sync(0xffffffffu, mdx, k);
        const float dy = __shfl_sync(0xffffffffu, mdy, k);
        const float dz = __shfl_sync(0xffffffffu, mdz, k);
        const float4* kv = (const float4*)(qkvg + (size_t)(gbase + idx) * 1024);
        const float4 kk0 = kv[64 + lane],  kk1 = kv[96 + lane];
        const float4 v0  = kv[128 + lane], v1  = kv[160 + lane];
        float4 h0, h1;
        h0.x = fmaxf(0.f, dx*w00.x + dy*w01.x + dz*w02.x + b0v.x);
        h0.y = fmaxf(0.f, dx*w00.y + dy*w01.y + dz*w02.y + b0v.y);
        h0.z = fmaxf(0.f, dx*w00.z + dy*w01.z + dz*w02.z + b0v.z);
        h0.w = fmaxf(0.f, dx*w00.w + dy*w01.w + dz*w02.w + b0v.w);
        h1.x = fmaxf(0.f, dx*w10.x + dy*w11.x + dz*w12.x + b1v.x);
        h1.y = fmaxf(0.f, dx*w10.y + dy*w11.y + dz*w12.y + b1v.y);
        h1.z = fmaxf(0.f, dx*w10.z + dy*w11.z + dz*w12.z + b1v.z);
        h1.w = fmaxf(0.f, dx*w10.w + dy*w11.w + dz*w12.w + b1v.w);
        float p = q0.x*kk0.x + q0.y*kk0.y + q0.z*kk0.z + q0.w*kk0.w
                + q1.x*kk1.x + q1.y*kk1.y + q1.z*kk1.z + q1.w*kk1.w
                + h0.x*gg0.x + h0.y*gg0.y + h0.z*gg0.z + h0.w*gg0.w
                + h1.x*gg1.x + h1.y*gg1.y + h1.z*gg1.z + h1.w*gg1.w;
        #pragma unroll
        for (int off = 16; off; off >>= 1) p += __shfl_xor_sync(0xffffffffu, p, off);
        p *= 0.0625f;

        const float mn = fmaxf(m, p);
        const float corr = __expf(m - mn);
        const float a = __expf(p - mn);
        m = mn;
        s = s * corr + a;
        sv0.x = sv0.x*corr + a*v0.x; sv0.y = sv0.y*corr + a*v0.y;
        sv0.z = sv0.z*corr + a*v0.z; sv0.w = sv0.w*corr + a*v0.w;
        sv1.x = sv1.x*corr + a*v1.x; sv1.y = sv1.y*corr + a*v1.y;
        sv1.z = sv1.z*corr + a*v1.z; sv1.w = sv1.w*corr + a*v1.w;
        A0.x = A0.x*corr + a*h0.x; A0.y = A0.y*corr + a*h0.y;
        A0.z = A0.z*corr + a*h0.z; A0.w = A0.w*corr + a*h0.w;
        A1.x = A1.x*corr + a*h1.x; A1.y = A1.y*corr + a*h1.y;
        A1.z = A1.z*corr + a*h1.z; A1.w = A1.w*corr + a*h1.w;
    }

    const float inv = 1.f / s;
    sv0.x *= inv; sv0.y *= inv; sv0.z *= inv; sv0.w *= inv;
    sv1.x *= inv; sv1.y *= inv; sv1.z *= inv; sv1.w *= inv;
    A0.x *= inv; A0.y *= inv; A0.z *= inv; A0.w *= inv;
    A1.x *= inv; A1.y *= inv; A1.z *= inv; A1.w *= inv;

    float4* o = (float4*)(svA + (size_t)n * 512);
    o[lane] = sv0; o[32 + lane] = sv1; o[64 + lane] = A0; o[96 + lane] = A1;
}

// ---------------- launch -----------------------------------------------------
extern "C" void kernel_launch(void* const* d_in, const int* in_sizes, int n_in,
                              void* d_out, int out_size)
{
    const float* features = (const float*)d_in[0];
    const float* xyz      = (const float*)d_in[1];
    const float* fc1w     = (const float*)d_in[2];
    const float* fc1b     = (const float*)d_in[3];
    const float* fc2w     = (const float*)d_in[4];
    const float* fc2b     = (const float*)d_in[5];
    const float* fd1w     = (const float*)d_in[6];
    const float* fd1b     = (const float*)d_in[7];
    const float* fd2w     = (const float*)d_in[8];
    const float* fd2b     = (const float*)d_in[9];
    const float* wq       = (const float*)d_in[10];
    const float* wk       = (const float*)d_in[11];
    const float* wv       = (const float*)d_in[12];
    float* out = (float*)d_out;

    void *p_qkvg, *p_svA, *p_knn, *p_Wbig, *p_W1big, *p_bvec, *p_W2, *p_cvec,
         *p_fd2T, *p_G;
    cudaGetSymbolAddress(&p_qkvg, g_qkvg);
    cudaGetSymbolAddress(&p_svA, g_svA);
    cudaGetSymbolAddress(&p_knn, g_knn);
    cudaGetSymbolAddress(&p_Wbig, g_Wbig);
    cudaGetSymbolAddress(&p_W1big, g_W1big);
    cudaGetSymbolAddress(&p_bvec, g_bvec);
    cudaGetSymbolAddress(&p_W2, g_W2);
    cudaGetSymbolAddress(&p_cvec, g_cvec);
    cudaGetSymbolAddress(&p_fd2T, g_fd2T);
    cudaGetSymbolAddress(&p_G, g_G);

    // ---- prep folded weights ----
    transpose256_k<<<dim3(8,8), dim3(32,8)>>>(fd2w, (float*)p_fd2T);
    // G = wq @ fd2^T
    sgemm_k<0><<<dim3(2, 2), 256>>>(wq, (const float*)p_fd2T, nullptr,
                                    (float*)p_G, 256, 256, 256, nullptr, nullptr);
    pack_wbig_k<<<1024, 256>>>(wq, wk, wv, (const float*)p_G, (float*)p_Wbig);
    // W1big = fc1 @ Wbig  (fc1 has no nonlinearity -> fold into one GEMM)
    sgemm_k<0><<<dim3(8, 1), 256>>>(fc1w, (const float*)p_Wbig, nullptr,
                                    (float*)p_W1big, 128, 1024, 256, nullptr, nullptr);
    bvec_k<<<4, 256>>>(fc1b, (const float*)p_Wbig, (float*)p_bvec);
    prep_w2_k<<<256, 256>>>(fc2w, fd2w, fd2b, fc2b, (float*)p_W2, (float*)p_cvec);

    // ---- KNN ----
    cudaFuncSetAttribute((const void*)knn_kernel,
                         cudaFuncAttributeMaxDynamicSharedMemorySize, 65536);
    knn_kernel<<<dim3(128, BB), 256, 65536>>>(xyz, (int*)p_knn);

    // ---- [q|k|v|g] = features @ W1big + bvec ----
    sgemm_k<0><<<dim3(8, 128), 256>>>(features, (const float*)p_W1big,
                                      (const float*)p_bvec, (float*)p_qkvg,
                                      TOT, 1024, 128, nullptr, nullptr);
    // ---- attention -> [sv|A] ----
    attn_k<<<2048, 256>>>((const float*)p_qkvg, xyz, (const int*)p_knn,
                          fd1w, fd1b, (float*)p_svA);
    // ---- out = [sv|A] @ [fc2; fd2@fc2] + cvec + features, transposed store ----
    sgemm_k<1><<<dim3(1, 128), 256>>>((const float*)p_svA, (const float*)p_W2,
                                      (const float*)p_cvec, nullptr,
                                      TOT, 128, 512, features, out);
}

// round 5
// speedup vs baseline: 2.6253x; 2.0465x over previous
#include <cuda_runtime.h>
#include <cfloat>
#include <cstdint>

// Problem constants
#define BB   4
#define NPTS 4096
#define KNN  16
#define DP   128
#define DM   256
#define TOT  (BB*NPTS)   // 16384
#define FULLMASK 0xffffffffu

// ---------------- scratch (static device globals; no allocation) ------------
__device__ __align__(64) float g_qkvg[(size_t)TOT*1024];     // 64 MB: [q|k|v|g]
__device__ __align__(64) float g_svA[(size_t)TOT*512];       // 32 MB: [sv|A]
__device__ __align__(64) int   g_knn[(size_t)TOT*KNN];
__device__ __align__(64) float g_W1big[128*1024];            // fc1 @ [wq|wk|wv|wq@fd2^T]
__device__ __align__(64) float g_bvec[1024];                 // fc1_b @ Wbig
__device__ __align__(64) float g_W2[512*128];                // [fc2 ; fd2@fc2]
__device__ __align__(64) float g_cvec[128];                  // fd2_b@fc2 + fc2_b

// ---------------- small-tile GEMM for weight prep ----------------------------
// C[M,N] = A[M,K] @ op(B), tile 64x64, 4x4 per thread, 256 threads.
// TRANSB=0: B is [K,N] row-major (ldb = row stride)
// TRANSB=1: B is [N,K] row-major (C = A @ B^T)
template <int TRANSB>
__global__ __launch_bounds__(256)
void gemm64_k(const float* __restrict__ A, int lda,
              const float* __restrict__ B, int ldb,
              float* __restrict__ C, int ldc, int K)
{
    __shared__ float As[16][68];
    __shared__ float Bs[16][68];
    const int tid = threadIdx.x;
    const int tx = tid & 15, ty = tid >> 4;
    const int bm = blockIdx.y * 64, bn = blockIdx.x * 64;

    const int ar = tid >> 2, ak = (tid & 3) << 2;   // A: row ar, k-chunk ak
    const int bk = tid >> 4, bn4 = (tid & 15) << 2; // B(NN): k-row bk, col bn4

    float acc[4][4];
    #pragma unroll
    for (int i = 0; i < 4; ++i)
        #pragma unroll
        for (int j = 0; j < 4; ++j) acc[i][j] = 0.f;

    for (int k0 = 0; k0 < K; k0 += 16) {
        float4 av = *(const float4*)(A + (size_t)(bm + ar) * lda + k0 + ak);
        float4 bv;
        if (TRANSB) bv = *(const float4*)(B + (size_t)(bn + ar) * ldb + k0 + ak);
        else        bv = *(const float4*)(B + (size_t)(k0 + bk) * ldb + bn + bn4);
        __syncthreads();
        As[ak+0][ar] = av.x; As[ak+1][ar] = av.y; As[ak+2][ar] = av.z; As[ak+3][ar] = av.w;
        if (TRANSB) {
            Bs[ak+0][ar] = bv.x; Bs[ak+1][ar] = bv.y; Bs[ak+2][ar] = bv.z; Bs[ak+3][ar] = bv.w;
        } else {
            *(float4*)&Bs[bk][bn4] = bv;
        }
        __syncthreads();
        #pragma unroll
        for (int kk = 0; kk < 16; ++kk) {
            float4 a = *(const float4*)&As[kk][ty << 2];
            float4 b = *(const float4*)&Bs[kk][tx << 2];
            float av4[4] = {a.x,a.y,a.z,a.w};
            float bv4[4] = {b.x,b.y,b.z,b.w};
            #pragma unroll
            for (int i = 0; i < 4; ++i)
                #pragma unroll
                for (int j = 0; j < 4; ++j)
                    acc[i][j] = fmaf(av4[i], bv4[j], acc[i][j]);
        }
    }
    #pragma unroll
    for (int i = 0; i < 4; ++i) {
        int r = bm + (ty << 2) + i;
        *(float4*)(C + (size_t)r * ldc + bn + (tx << 2)) =
            make_float4(acc[i][0], acc[i][1], acc[i][2], acc[i][3]);
    }
}

// ---------------- tiny prep kernels -----------------------------------------
__global__ void copy_k(const float* __restrict__ src, float* __restrict__ dst, int n)
{
    int i = blockIdx.x * blockDim.x + threadIdx.x;
    if (i < n) dst[i] = src[i];
}

// bvec = fc1_b @ [wq|wk|wv|wq@fd2^T]
__global__ void bvec_k(const float* __restrict__ fc1b, const float* __restrict__ wq,
                       const float* __restrict__ wk, const float* __restrict__ wv,
                       const float* __restrict__ fd2, float* __restrict__ bvec)
{
    __shared__ float sv[256];
    const int blk = blockIdx.x, t = threadIdx.x;
    if (blk < 3) {
        const float* w = blk == 0 ? wq : (blk == 1 ? wk : wv);
        float s = 0.f;
        for (int d = 0; d < 256; ++d) s += fc1b[d] * w[d*256 + t];
        bvec[blk*256 + t] = s;
    } else {
        float s = 0.f;
        for (int d = 0; d < 256; ++d) s += fc1b[d] * wq[d*256 + t];
        sv[t] = s;
        __syncthreads();
        float s2 = 0.f;
        for (int d = 0; d < 256; ++d) s2 += sv[d] * fd2[t*256 + d];
        bvec[768 + t] = s2;
    }
}

__global__ void cvec_k(const float* __restrict__ fc2, const float* __restrict__ fd2b,
                       const float* __restrict__ fc2b, float* __restrict__ cvec)
{
    int c = threadIdx.x;   // 128
    float s = fc2b[c];
    for (int d = 0; d < 256; ++d) s += fd2b[d] * fc2[d*128 + c];
    cvec[c] = s;
}

// ---------------- KNN: warp-distributed sorted top-16 ------------------------
// grid (128, B), block 256, dyn smem 64KB. 1 warp per query.
// Lanes 0..15 hold the running top-16 (ascending lexicographic (d, idx)).
// Candidate only enters if it beats the broadcast 16th-best -> ~100 inserts total.
__global__ __launch_bounds__(256)
void knn_kernel(const float* __restrict__ xyz, int* __restrict__ knn)
{
    extern __shared__ float sh[];
    float* sx = sh;
    float* sy = sh + NPTS;
    float* sz = sh + 2*NPTS;
    float* sq = sh + 3*NPTS;
    const int b = blockIdx.y;
    const float* xb = xyz + (size_t)b * NPTS * 3;
    for (int p = threadIdx.x; p < NPTS; p += blockDim.x) {
        float x = xb[3*p], y = xb[3*p+1], z = xb[3*p+2];
        sx[p] = x; sy[p] = y; sz[p] = z;
        sq[p] = x*x + y*y + z*z;
    }
    __syncthreads();

    const int warp = threadIdx.x >> 5, lane = threadIdx.x & 31;
    for (int qi = warp; qi < 32; qi += 8) {
        const int qn = blockIdx.x * 32 + qi;
        const float qx = sx[qn], qy = sy[qn], qz = sz[qn], qs = sq[qn];

        float ld = FLT_MAX; int li = 0x7fffffff;      // this lane's list slot
        float thd = FLT_MAX; int thi = 0x7fffffff;    // broadcast 16th-best

        for (int c0 = 0; c0 < NPTS; c0 += 32) {
            const int c = c0 + lane;
            const float dot = qx*sx[c] + qy*sy[c] + qz*sz[c];
            const float d = (qs + sq[c]) - 2.0f * dot;
            unsigned mask = __ballot_sync(FULLMASK, d < thd || (d == thd && c < thi));
            while (mask) {
                const int src = __ffs(mask) - 1;
                mask &= mask - 1;
                const float cd = __shfl_sync(FULLMASK, d, src);
                const int ci = c0 + src;
                if (cd < thd || (cd == thd && ci < thi)) {
                    const bool lt = (ld < cd) || (ld == cd && li < ci);
                    const int pos = __popc(__ballot_sync(FULLMASK, lt) & 0xFFFFu);
                    const float pd = __shfl_up_sync(FULLMASK, ld, 1);
                    const int pi = __shfl_up_sync(FULLMASK, li, 1);
                    if ((int)lane > pos) { ld = pd; li = pi; }
                    else if ((int)lane == pos) { ld = cd; li = ci; }
                    thd = __shfl_sync(FULLMASK, ld, 15);
                    thi = __shfl_sync(FULLMASK, li, 15);
                } else {
                    // keep shfl participation uniform (no-op path)
                    __shfl_up_sync(FULLMASK, ld, 1);
                    __shfl_up_sync(FULLMASK, li, 1);
                    __shfl_sync(FULLMASK, ld, 15);
                    __shfl_sync(FULLMASK, li, 15);
                }
            }
        }

        if (lane < 16) knn[((size_t)(b*NPTS + qn)) * KNN + lane] = li;
    }
}

// ---------------- fp32 SGEMM: 128x128 tile, 8x8/thread (qkvg) ---------------
__global__ __launch_bounds__(256)
void sgemm_k(const float* __restrict__ A, const float* __restrict__ Bm,
             const float* __restrict__ bias, float* __restrict__ C,
             int M, int N, int K)
{
    __shared__ float As[16][132];
    __shared__ float Bs[16][128];
    const int tid = threadIdx.x;
    const int tx = tid & 15, ty = tid >> 4;
    const int bm = blockIdx.y * 128, bn = blockIdx.x * 128;

    const int ar0 = tid >> 2, ac = (tid & 3) << 2;
    const int br0 = tid >> 5, bc = (tid & 31) << 2;

    float acc[8][8];
    #pragma unroll
    for (int i = 0; i < 8; ++i)
        #pragma unroll
        for (int j = 0; j < 8; ++j) acc[i][j] = 0.f;

    const float* Ap0 = A + (size_t)(bm + ar0) * K + ac;
    const float* Ap1 = Ap0 + (size_t)64 * K;
    const float* Bp0 = Bm + (size_t)br0 * N + bn + bc;
    const float* Bp1 = Bp0 + (size_t)8 * N;

    for (int k0 = 0; k0 < K; k0 += 16) {
        float4 av0 = *(const float4*)(Ap0 + k0);
        float4 av1 = *(const float4*)(Ap1 + k0);
        float4 bv0 = *(const float4*)(Bp0 + (size_t)k0 * N);
        float4 bv1 = *(const float4*)(Bp1 + (size_t)k0 * N);
        __syncthreads();
        As[ac+0][ar0] = av0.x; As[ac+1][ar0] = av0.y; As[ac+2][ar0] = av0.z; As[ac+3][ar0] = av0.w;
        As[ac+0][ar0+64] = av1.x; As[ac+1][ar0+64] = av1.y; As[ac+2][ar0+64] = av1.z; As[ac+3][ar0+64] = av1.w;
        *(float4*)&Bs[br0][bc] = bv0;
        *(float4*)&Bs[br0+8][bc] = bv1;
        __syncthreads();
        #pragma unroll
        for (int kk = 0; kk < 16; ++kk) {
            float4 a0 = *(const float4*)&As[kk][ty << 2];
            float4 a1 = *(const float4*)&As[kk][(ty << 2) + 64];
            float4 b0 = *(const float4*)&Bs[kk][tx << 2];
            float4 b1 = *(const float4*)&Bs[kk][(tx << 2) + 64];
            float a[8] = {a0.x,a0.y,a0.z,a0.w, a1.x,a1.y,a1.z,a1.w};
            float bvals[8] = {b0.x,b0.y,b0.z,b0.w, b1.x,b1.y,b1.z,b1.w};
            #pragma unroll
            for (int i = 0; i < 8; ++i)
                #pragma unroll
                for (int j = 0; j < 8; ++j)
                    acc[i][j] = fmaf(a[i], bvals[j], acc[i][j]);
        }
    }

    float4 bb0 = *(const float4*)(bias + bn + (tx << 2));
    float4 bb1 = *(const float4*)(bias + bn + (tx << 2) + 64);

    #pragma unroll
    for (int i = 0; i < 8; ++i) {
        int r = bm + (ty << 2) + (i & 3) + ((i & 4) << 4);
        float4 o0 = make_float4(acc[i][0]+bb0.x, acc[i][1]+bb0.y, acc[i][2]+bb0.z, acc[i][3]+bb0.w);
        float4 o1 = make_float4(acc[i][4]+bb1.x, acc[i][5]+bb1.y, acc[i][6]+bb1.z, acc[i][7]+bb1.w);
        *(float4*)(C + (size_t)r * N + bn + (tx << 2)) = o0;
        *(float4*)(C + (size_t)r * N + bn + (tx << 2) + 64) = o1;
    }
}

// ---------------- final GEMM: 64x64 tile + residual + transposed store ------
// C = svA[16384,512] @ W2[512,128] + cvec + features; out[b, c, n] coalesced.
__global__ __launch_bounds__(256)
void gemm_final_k(const float* __restrict__ A, const float* __restrict__ Bm,
                  const float* __restrict__ bias, const float* __restrict__ resid,
                  float* __restrict__ outT)
{
    __shared__ float As[16][68];
    __shared__ float Bs[16][68];
    __shared__ float Ts[64][65];
    const int tid = threadIdx.x;
    const int tx = tid & 15, ty = tid >> 4;
    const int bm = blockIdx.y * 64, bn = blockIdx.x * 64;
    const int K = 512, lda = 512, ldb = 128;

    const int ar = tid >> 2, ak = (tid & 3) << 2;
    const int bk = tid >> 4, bn4 = (tid & 15) << 2;

    float acc[4][4];
    #pragma unroll
    for (int i = 0; i < 4; ++i)
        #pragma unroll
        for (int j = 0; j < 4; ++j) acc[i][j] = 0.f;

    for (int k0 = 0; k0 < K; k0 += 16) {
        float4 av = *(const float4*)(A + (size_t)(bm + ar) * lda + k0 + ak);
        float4 bv = *(const float4*)(Bm + (size_t)(k0 + bk) * ldb + bn + bn4);
        __syncthreads();
        As[ak+0][ar] = av.x; As[ak+1][ar] = av.y; As[ak+2][ar] = av.z; As[ak+3][ar] = av.w;
        *(float4*)&Bs[bk][bn4] = bv;
        __syncthreads();
        #pragma unroll
        for (int kk = 0; kk < 16; ++kk) {
            float4 a = *(const float4*)&As[kk][ty << 2];
            float4 b = *(const float4*)&Bs[kk][tx << 2];
            float av4[4] = {a.x,a.y,a.z,a.w};
            float bv4[4] = {b.x,b.y,b.z,b.w};
            #pragma unroll
            for (int i = 0; i < 4; ++i)
                #pragma unroll
                for (int j = 0; j < 4; ++j)
                    acc[i][j] = fmaf(av4[i], bv4[j], acc[i][j]);
        }
    }

    const float4 bb = *(const float4*)(bias + bn + (tx << 2));
    #pragma unroll
    for (int i = 0; i < 4; ++i) {
        const int r = bm + (ty << 2) + i;
        const float4 fr = *(const float4*)(resid + (size_t)r * 128 + bn + (tx << 2));
        Ts[(tx<<2)+0][(ty<<2)+i] = acc[i][0] + bb.x + fr.x;
        Ts[(tx<<2)+1][(ty<<2)+i] = acc[i][1] + bb.y + fr.y;
        Ts[(tx<<2)+2][(ty<<2)+i] = acc[i][2] + bb.z + fr.z;
        Ts[(tx<<2)+3][(ty<<2)+i] = acc[i][3] + bb.w + fr.w;
    }
    __syncthreads();

    // write out[b, c, n]: row r2 = channel, 64 consecutive n values
    const int bidx = bm >> 12;
    const int nn0 = bm & 4095;
    const int r2 = tid >> 2, seg = (tid & 3) << 4;
    float* obase = outT + ((size_t)bidx << 19) + ((size_t)(bn + r2) << 12) + nn0 + seg;
    #pragma unroll
    for (int q = 0; q < 4; ++q) {
        *(float4*)(obase + (q << 2)) =
            make_float4(Ts[r2][seg + (q<<2)], Ts[r2][seg + (q<<2) + 1],
                        Ts[r2][seg + (q<<2) + 2], Ts[r2][seg + (q<<2) + 3]);
    }
}

// ---------------- fused neighborhood attention (single pass, prefetch) ------
__global__ __launch_bounds__(256)
void attn_k(const float* __restrict__ qkvg, const float* __restrict__ xyz,
            const int* __restrict__ knn, const float* __restrict__ fd1w,
            const float* __restrict__ fd1b, float* __restrict__ svA)
{
    __shared__ float sw[768];
    __shared__ float sb[256];
    const int tid = threadIdx.x;
    for (int i = tid; i < 768; i += 256) sw[i] = fd1w[i];
    for (int i = tid; i < 256; i += 256) sb[i] = fd1b[i];
    __syncthreads();

    const int lane = tid & 31, warp = tid >> 5;
    const int n = blockIdx.x * 8 + warp;
    const int gbase = n & ~(NPTS - 1);

    const float4* qv = (const float4*)(qkvg + (size_t)n * 1024);
    const float4 q0 = qv[lane],        q1 = qv[32 + lane];
    const float4 gg0 = qv[192 + lane], gg1 = qv[224 + lane];

    const int c0 = lane << 2;
    const float4 w00 = *(const float4*)(sw + c0);
    const float4 w01 = *(const float4*)(sw + 256 + c0);
    const float4 w02 = *(const float4*)(sw + 512 + c0);
    const float4 b0v = *(const float4*)(sb + c0);
    const float4 w10 = *(const float4*)(sw + c0 + 128);
    const float4 w11 = *(const float4*)(sw + 256 + c0 + 128);
    const float4 w12 = *(const float4*)(sw + 512 + c0 + 128);
    const float4 b1v = *(const float4*)(sb + c0 + 128);

    const float px = xyz[(size_t)n*3], py = xyz[(size_t)n*3+1], pz = xyz[(size_t)n*3+2];
    int myidx = 0; float mdx = 0.f, mdy = 0.f, mdz = 0.f;
    if (lane < 16) {
        myidx = knn[(size_t)n * KNN + lane];
        const float* nb = xyz + (size_t)(gbase + myidx) * 3;
        mdx = px - nb[0]; mdy = py - nb[1]; mdz = pz - nb[2];
    }

    float m = -FLT_MAX, s = 0.f;
    float4 sv0 = make_float4(0,0,0,0), sv1 = sv0, A0 = sv0, A1 = sv0;

    // prefetch k=0
    int cidx = __shfl_sync(FULLMASK, myidx, 0);
    const float4* cp = (const float4*)(qkvg + (size_t)(gbase + cidx) * 1024);
    float4 ck0 = __ldg(cp + 64 + lane),  ck1 = __ldg(cp + 96 + lane);
    float4 cv0 = __ldg(cp + 128 + lane), cv1 = __ldg(cp + 160 + lane);

    #pragma unroll
    for (int k = 0; k < 16; ++k) {
        float4 nk0, nk1, nv0, nv1;
        if (k < 15) {
            const int nidx = __shfl_sync(FULLMASK, myidx, k + 1);
            const float4* np = (const float4*)(qkvg + (size_t)(gbase + nidx) * 1024);
            nk0 = __ldg(np + 64 + lane);  nk1 = __ldg(np + 96 + lane);
            nv0 = __ldg(np + 128 + lane); nv1 = __ldg(np + 160 + lane);
        }
        const float dx = __shfl_sync(FULLMASK, mdx, k);
        const float dy = __shfl_sync(FULLMASK, mdy, k);
        const float dz = __shfl_sync(FULLMASK, mdz, k);
        float4 h0, h1;
        h0.x = fmaxf(0.f, dx*w00.x + dy*w01.x + dz*w02.x + b0v.x);
        h0.y = fmaxf(0.f, dx*w00.y + dy*w01.y + dz*w02.y + b0v.y);
        h0.z = fmaxf(0.f, dx*w00.z + dy*w01.z + dz*w02.z + b0v.z);
        h0.w = fmaxf(0.f, dx*w00.w + dy*w01.w + dz*w02.w + b0v.w);
        h1.x = fmaxf(0.f, dx*w10.x + dy*w11.x + dz*w12.x + b1v.x);
        h1.y = fmaxf(0.f, dx*w10.y + dy*w11.y + dz*w12.y + b1v.y);
        h1.z = fmaxf(0.f, dx*w10.z + dy*w11.z + dz*w12.z + b1v.z);
        h1.w = fmaxf(0.f, dx*w10.w + dy*w11.w + dz*w12.w + b1v.w);
        float p = q0.x*ck0.x + q0.y*ck0.y + q0.z*ck0.z + q0.w*ck0.w
                + q1.x*ck1.x + q1.y*ck1.y + q1.z*ck1.z + q1.w*ck1.w
                + h0.x*gg0.x + h0.y*gg0.y + h0.z*gg0.z + h0.w*gg0.w
                + h1.x*gg1.x + h1.y*gg1.y + h1.z*gg1.z + h1.w*gg1.w;
        #pragma unroll
        for (int off = 16; off; off >>= 1) p += __shfl_xor_sync(FULLMASK, p, off);
        p *= 0.0625f;

        const float mn = fmaxf(m, p);
        const float corr = __expf(m - mn);
        const float a = __expf(p - mn);
        m = mn;
        s = s * corr + a;
        sv0.x = sv0.x*corr + a*cv0.x; sv0.y = sv0.y*corr + a*cv0.y;
        sv0.z = sv0.z*corr + a*cv0.z; sv0.w = sv0.w*corr + a*cv0.w;
        sv1.x = sv1.x*corr + a*cv1.x; sv1.y = sv1.y*corr + a*cv1.y;
        sv1.z = sv1.z*corr + a*cv1.z; sv1.w = sv1.w*corr + a*cv1.w;
        A0.x = A0.x*corr + a*h0.x; A0.y = A0.y*corr + a*h0.y;
        A0.z = A0.z*corr + a*h0.z; A0.w = A0.w*corr + a*h0.w;
        A1.x = A1.x*corr + a*h1.x; A1.y = A1.y*corr + a*h1.y;
        A1.z = A1.z*corr + a*h1.z; A1.w = A1.w*corr + a*h1.w;
        ck0 = nk0; ck1 = nk1; cv0 = nv0; cv1 = nv1;
    }

    const float inv = 1.f / s;
    sv0.x *= inv; sv0.y *= inv; sv0.z *= inv; sv0.w *= inv;
    sv1.x *= inv; sv1.y *= inv; sv1.z *= inv; sv1.w *= inv;
    A0.x *= inv; A0.y *= inv; A0.z *= inv; A0.w *= inv;
    A1.x *= inv; A1.y *= inv; A1.z *= inv; A1.w *= inv;

    float4* o = (float4*)(svA + (size_t)n * 512);
    o[lane] = sv0; o[32 + lane] = sv1; o[64 + lane] = A0; o[96 + lane] = A1;
}

// ---------------- launch -----------------------------------------------------
extern "C" void kernel_launch(void* const* d_in, const int* in_sizes, int n_in,
                              void* d_out, int out_size)
{
    const float* features = (const float*)d_in[0];
    const float* xyz      = (const float*)d_in[1];
    const float* fc1w     = (const float*)d_in[2];
    const float* fc1b     = (const float*)d_in[3];
    const float* fc2w     = (const float*)d_in[4];
    const float* fc2b     = (const float*)d_in[5];
    const float* fd1w     = (const float*)d_in[6];
    const float* fd1b     = (const float*)d_in[7];
    const float* fd2w     = (const float*)d_in[8];
    const float* fd2b     = (const float*)d_in[9];
    const float* wq       = (const float*)d_in[10];
    const float* wk       = (const float*)d_in[11];
    const float* wv       = (const float*)d_in[12];
    float* out = (float*)d_out;

    void *p_qkvg, *p_svA, *p_knn, *p_W1big, *p_bvec, *p_W2, *p_cvec;
    cudaGetSymbolAddress(&p_qkvg, g_qkvg);
    cudaGetSymbolAddress(&p_svA, g_svA);
    cudaGetSymbolAddress(&p_knn, g_knn);
    cudaGetSymbolAddress(&p_W1big, g_W1big);
    cudaGetSymbolAddress(&p_bvec, g_bvec);
    cudaGetSymbolAddress(&p_W2, g_W2);
    cudaGetSymbolAddress(&p_cvec, g_cvec);
    float* W1big = (float*)p_W1big;
    float* W2 = (float*)p_W2;

    // ---- KNN first (independent of weight prep) ----
    cudaFuncSetAttribute((const void*)knn_kernel,
                         cudaFuncAttributeMaxDynamicSharedMemorySize, 65536);
    knn_kernel<<<dim3(128, BB), 256, 65536>>>(xyz, (int*)p_knn);

    // ---- prep folded weights (small-tile GEMMs, no transposes) ----
    // W1big[:,0:256] = fc1@wq ; [:,256:512] = fc1@wk ; [:,512:768] = fc1@wv
    gemm64_k<0><<<dim3(4, 2), 256>>>(fc1w, 256, wq, 256, W1big + 0,   1024, 256);
    gemm64_k<0><<<dim3(4, 2), 256>>>(fc1w, 256, wk, 256, W1big + 256, 1024, 256);
    gemm64_k<0><<<dim3(4, 2), 256>>>(fc1w, 256, wv, 256, W1big + 512, 1024, 256);
    // W1big[:,768:1024] = (fc1@wq) @ fd2^T
    gemm64_k<1><<<dim3(4, 2), 256>>>(W1big, 1024, fd2w, 256, W1big + 768, 1024, 256);
    // W2[0:256,:] = fc2 ; W2[256:512,:] = fd2@fc2
    copy_k<<<128, 256>>>(fc2w, W2, 256*128);
    gemm64_k<0><<<dim3(2, 4), 256>>>(fd2w, 256, fc2w, 128, W2 + 256*128, 128, 256);
    bvec_k<<<4, 256>>>(fc1b, wq, wk, wv, fd2w, (float*)p_bvec);
    cvec_k<<<1, 128>>>(fc2w, fd2b, fc2b, (float*)p_cvec);

    // ---- [q|k|v|g] = features @ W1big + bvec ----
    sgemm_k<<<dim3(8, 128), 256>>>(features, W1big, (const float*)p_bvec,
                                   (float*)p_qkvg, TOT, 1024, 128);
    // ---- attention -> [sv|A] ----
    attn_k<<<2048, 256>>>((const float*)p_qkvg, xyz, (const int*)p_knn,
                          fd1w, fd1b, (float*)p_svA);
    // ---- out = [sv|A] @ W2 + cvec + features, coalesced transposed store ----
    gemm_final_k<<<dim3(2, 256), 256>>>((const float*)p_svA, W2,
                                        (const float*)p_cvec, features, out);
}

// round 6
// speedup vs baseline: 3.7189x; 1.4166x over previous
#include <cuda_runtime.h>
#include <cfloat>
#include <cstdint>

// Problem constants
#define BB   4
#define NPTS 4096
#define KNN  16
#define DP   128
#define DM   256
#define TOT  (BB*NPTS)   // 16384
#define FULLMASK 0xffffffffu

// ---------------- scratch (static device globals; no allocation) ------------
__device__ __align__(64) float g_qkvg[(size_t)TOT*1024];     // [q|k|v|g]
__device__ __align__(64) float g_svA[(size_t)TOT*512];       // [sv|A]
__device__ __align__(64) int   g_knn[(size_t)TOT*KNN];
__device__ __align__(64) float g_W1big[128*1024];            // fc1 @ [wq|wk|wv|wq@fd2^T]
__device__ __align__(64) float g_bvec[1024];
__device__ __align__(64) float g_W2[512*128];                // [fc2 ; fd2@fc2]
__device__ __align__(64) float g_cvec[128];

// ---------------- tf32 helpers ----------------------------------------------
__device__ __forceinline__ float f2tf32(float x)
{
    unsigned r;
    asm("cvt.rna.tf32.f32 %0, %1;" : "=r"(r) : "f"(x));
    return __uint_as_float(r);
}

__device__ __forceinline__ void mma_tf32(float* c, const unsigned* a, const unsigned* b)
{
    asm volatile(
        "mma.sync.aligned.m16n8k8.row.col.f32.tf32.tf32.f32 "
        "{%0,%1,%2,%3}, {%4,%5,%6,%7}, {%8,%9}, {%0,%1,%2,%3};"
        : "+f"(c[0]), "+f"(c[1]), "+f"(c[2]), "+f"(c[3])
        : "r"(a[0]), "r"(a[1]), "r"(a[2]), "r"(a[3]), "r"(b[0]), "r"(b[1]));
}

// ---------------- TF32 tensor-core GEMM --------------------------------------
// C[M,N] = A[M,K]@B[K,N] + bias, 128x128 CTA tile, 8 warps (2x4), warp 64x32.
// EPI=0: direct store. EPI=1: N==128, add resid, transpose-store out[b,c,n].
// Dynamic smem: EPI0 35840B (As 128x36 + Bs 32x136), EPI1 67584B (Ts 128x132).
#define AS_PITCH 36
#define BS_PITCH 136
#define TS_PITCH 132

template <int EPI>
__global__ __launch_bounds__(256)
void tf32gemm_k(const float* __restrict__ A, const float* __restrict__ B,
                const float* __restrict__ bias, float* __restrict__ C,
                int M, int N, int K, const float* __restrict__ resid)
{
    extern __shared__ float smem[];
    float* As = smem;                 // [128][36]
    float* Bs = smem + 128*AS_PITCH;  // [32][136]

    const int tid = threadIdx.x;
    const int lane = tid & 31, warp = tid >> 5;
    const int g = lane >> 2, t = lane & 3;
    const int wm = (warp >> 2) * 64, wn = (warp & 3) * 32;
    const int bm = blockIdx.y * 128, bn = blockIdx.x * 128;

    float acc[4][4][4];
    #pragma unroll
    for (int mf = 0; mf < 4; ++mf)
        #pragma unroll
        for (int nf = 0; nf < 4; ++nf)
            #pragma unroll
            for (int i = 0; i < 4; ++i) acc[mf][nf][i] = 0.f;

    const int arow = tid >> 1;            // 0..127
    const int acol0 = (tid & 1) * 16;     // 0 or 16
    const int brow = tid >> 3;            // 0..31
    const int bcol0 = (tid & 7) * 4;      // 0..28

    for (int k0 = 0; k0 < K; k0 += 32) {
        float4 av[4], bv[4];
        #pragma unroll
        for (int i = 0; i < 4; ++i)
            av[i] = *(const float4*)(A + (size_t)(bm + arow) * K + k0 + acol0 + 4*i);
        #pragma unroll
        for (int i = 0; i < 4; ++i)
            bv[i] = *(const float4*)(B + (size_t)(k0 + brow) * N + bn + bcol0 + 32*i);
        __syncthreads();
        #pragma unroll
        for (int i = 0; i < 4; ++i) {
            float* d = As + arow*AS_PITCH + acol0 + 4*i;
            d[0] = f2tf32(av[i].x); d[1] = f2tf32(av[i].y);
            d[2] = f2tf32(av[i].z); d[3] = f2tf32(av[i].w);
        }
        #pragma unroll
        for (int i = 0; i < 4; ++i) {
            float* d = Bs + brow*BS_PITCH + bcol0 + 32*i;
            d[0] = f2tf32(bv[i].x); d[1] = f2tf32(bv[i].y);
            d[2] = f2tf32(bv[i].z); d[3] = f2tf32(bv[i].w);
        }
        __syncthreads();

        #pragma unroll
        for (int ks = 0; ks < 4; ++ks) {
            const int kb = ks * 8;
            unsigned a[4][4], b[4][2];
            #pragma unroll
            for (int mf = 0; mf < 4; ++mf) {
                const float* ap = As + (wm + mf*16 + g)*AS_PITCH + kb + t;
                a[mf][0] = __float_as_uint(ap[0]);
                a[mf][1] = __float_as_uint(ap[8*AS_PITCH]);
                a[mf][2] = __float_as_uint(ap[4]);
                a[mf][3] = __float_as_uint(ap[8*AS_PITCH + 4]);
            }
            #pragma unroll
            for (int nf = 0; nf < 4; ++nf) {
                const float* bp = Bs + (kb + t)*BS_PITCH + wn + nf*8 + g;
                b[nf][0] = __float_as_uint(bp[0]);
                b[nf][1] = __float_as_uint(bp[4*BS_PITCH]);
            }
            #pragma unroll
            for (int mf = 0; mf < 4; ++mf)
                #pragma unroll
                for (int nf = 0; nf < 4; ++nf)
                    mma_tf32(acc[mf][nf], a[mf], b[nf]);
        }
    }

    if (EPI == 0) {
        #pragma unroll
        for (int mf = 0; mf < 4; ++mf) {
            const int row = bm + wm + mf*16 + g;
            #pragma unroll
            for (int nf = 0; nf < 4; ++nf) {
                const int col = bn + wn + nf*8 + 2*t;
                const float2 bl = *(const float2*)(bias + col);
                *(float2*)(C + (size_t)row * N + col) =
                    make_float2(acc[mf][nf][0] + bl.x, acc[mf][nf][1] + bl.y);
                *(float2*)(C + (size_t)(row + 8) * N + col) =
                    make_float2(acc[mf][nf][2] + bl.x, acc[mf][nf][3] + bl.y);
            }
        }
    } else {
        __syncthreads();
        float* Ts = smem;   // [128 chan][132 pts]
        #pragma unroll
        for (int mf = 0; mf < 4; ++mf) {
            const int row = wm + mf*16 + g;
            #pragma unroll
            for (int nf = 0; nf < 4; ++nf) {
                const int col = wn + nf*8 + 2*t;
                const float2 bl = *(const float2*)(bias + col);
                const float2 f0 = *(const float2*)(resid + (size_t)(bm + row) * 128 + col);
                const float2 f1 = *(const float2*)(resid + (size_t)(bm + row + 8) * 128 + col);
                Ts[(col    )*TS_PITCH + row    ] = acc[mf][nf][0] + bl.x + f0.x;
                Ts[(col + 1)*TS_PITCH + row    ] = acc[mf][nf][1] + bl.y + f0.y;
                Ts[(col    )*TS_PITCH + row + 8] = acc[mf][nf][2] + bl.x + f1.x;
                Ts[(col + 1)*TS_PITCH + row + 8] = acc[mf][nf][3] + bl.y + f1.y;
            }
        }
        __syncthreads();
        const int bidx = bm >> 12, nn0 = bm & 4095;
        const int chan = tid >> 1, seg = (tid & 1) * 64;
        float* ob = C + ((size_t)bidx << 19) + ((size_t)chan << 12) + nn0 + seg;
        #pragma unroll
        for (int i = 0; i < 16; ++i) {
            const float* ts = Ts + chan*TS_PITCH + seg + 4*i;
            *(float4*)(ob + 4*i) = make_float4(ts[0], ts[1], ts[2], ts[3]);
        }
    }
}

// ---------------- gemm64 device body (weight prep) ---------------------------
template <int TRANSB>
__device__ __forceinline__ void gemm64_body(
    const float* __restrict__ A, int lda, const float* __restrict__ B, int ldb,
    float* __restrict__ C, int ldc, int K, int bm, int bn,
    float (*As)[68], float (*Bs)[68])
{
    const int tid = threadIdx.x;
    const int tx = tid & 15, ty = tid >> 4;
    const int ar = tid >> 2, ak = (tid & 3) << 2;
    const int bk = tid >> 4, bn4 = (tid & 15) << 2;

    float acc[4][4];
    #pragma unroll
    for (int i = 0; i < 4; ++i)
        #pragma unroll
        for (int j = 0; j < 4; ++j) acc[i][j] = 0.f;

    for (int k0 = 0; k0 < K; k0 += 16) {
        float4 av = *(const float4*)(A + (size_t)(bm + ar) * lda + k0 + ak);
        float4 bv;
        if (TRANSB) bv = *(const float4*)(B + (size_t)(bn + ar) * ldb + k0 + ak);
        else        bv = *(const float4*)(B + (size_t)(k0 + bk) * ldb + bn + bn4);
        __syncthreads();
        As[ak+0][ar] = av.x; As[ak+1][ar] = av.y; As[ak+2][ar] = av.z; As[ak+3][ar] = av.w;
        if (TRANSB) {
            Bs[ak+0][ar] = bv.x; Bs[ak+1][ar] = bv.y; Bs[ak+2][ar] = bv.z; Bs[ak+3][ar] = bv.w;
        } else {
            *(float4*)&Bs[bk][bn4] = bv;
        }
        __syncthreads();
        #pragma unroll
        for (int kk = 0; kk < 16; ++kk) {
            float4 a = *(const float4*)&As[kk][ty << 2];
            float4 b = *(const float4*)&Bs[kk][tx << 2];
            float av4[4] = {a.x,a.y,a.z,a.w};
            float bv4[4] = {b.x,b.y,b.z,b.w};
            #pragma unroll
            for (int i = 0; i < 4; ++i)
                #pragma unroll
                for (int j = 0; j < 4; ++j)
                    acc[i][j] = fmaf(av4[i], bv4[j], acc[i][j]);
        }
    }
    #pragma unroll
    for (int i = 0; i < 4; ++i) {
        int r = bm + (ty << 2) + i;
        *(float4*)(C + (size_t)r * ldc + bn + (tx << 2)) =
            make_float4(acc[i][0], acc[i][1], acc[i][2], acc[i][3]);
    }
}

// ---------------- fused weight prep (independent parts) ---------------------
// blocks 0..23 : W1big[:, t*256:(t+1)*256] = fc1 @ {wq,wk,wv}   (8 each)
// blocks 24..31: W2[256:512,:] = fd2 @ fc2
// blocks 32..35: W2[0:256,:] = fc2 (copy)
// block  36    : cvec = fd2_b@fc2 + fc2_b
// blocks 37..39: bvec[t*256:..] = fc1_b @ {wq,wk,wv}
__global__ __launch_bounds__(256)
void prep1_k(const float* __restrict__ fc1w, const float* __restrict__ wq,
             const float* __restrict__ wk, const float* __restrict__ wv,
             const float* __restrict__ fd2w, const float* __restrict__ fc2w,
             const float* __restrict__ fc1b, const float* __restrict__ fd2b,
             const float* __restrict__ fc2b,
             float* __restrict__ W1big, float* __restrict__ bvec,
             float* __restrict__ W2, float* __restrict__ cvec)
{
    __shared__ float As[16][68];
    __shared__ float Bs[16][68];
    const int bid = blockIdx.x;
    if (bid < 24) {
        const int task = bid >> 3, local = bid & 7;
        const float* W = task == 0 ? wq : (task == 1 ? wk : wv);
        gemm64_body<0>(fc1w, 256, W, 256, W1big + task*256, 1024, 256,
                       (local >> 2) * 64, (local & 3) * 64, As, Bs);
    } else if (bid < 32) {
        const int local = bid - 24;
        gemm64_body<0>(fd2w, 256, fc2w, 128, W2 + 256*128, 128, 256,
                       (local >> 1) * 64, (local & 1) * 64, As, Bs);
    } else if (bid < 36) {
        const int local = bid - 32;
        const float4* src = (const float4*)fc2w + local*2048 + threadIdx.x;
        float4* dst = (float4*)W2 + local*2048 + threadIdx.x;
        #pragma unroll
        for (int i = 0; i < 8; ++i) dst[i*256] = src[i*256];
    } else if (bid == 36) {
        if (threadIdx.x < 128) {
            const int c = threadIdx.x;
            float s = fc2b[c];
            for (int d = 0; d < 256; ++d) s += fd2b[d] * fc2w[d*128 + c];
            cvec[c] = s;
        }
    } else {
        const int blk = bid - 37;
        const float* w = blk == 0 ? wq : (blk == 1 ? wk : wv);
        const int c = threadIdx.x;
        float s = 0.f;
        for (int d = 0; d < 128; ++d) s += fc1b[d] * w[d*256 + c];
        bvec[blk*256 + c] = s;
    }
}

// dependent parts: g-block of W1big and bvec
// blocks 0..7: W1big[:,768:1024] = W1big[:,0:256] @ fd2^T
// block  8   : bvec[768:1024] = bvec[0:256] @ fd2^T
__global__ __launch_bounds__(256)
void prep2_k(const float* __restrict__ fd2w, float* __restrict__ W1big,
             float* __restrict__ bvec)
{
    __shared__ float As[16][68];
    __shared__ float Bs[16][68];
    const int bid = blockIdx.x;
    if (bid < 8) {
        gemm64_body<1>(W1big, 1024, fd2w, 256, W1big + 768, 1024, 256,
                       (bid >> 2) * 64, (bid & 3) * 64, As, Bs);
    } else {
        const int j = threadIdx.x;
        float s = 0.f;
        for (int d = 0; d < 256; ++d) s += bvec[d] * fd2w[j*256 + d];
        bvec[768 + j] = s;
    }
}

// ---------------- KNN: warp-distributed sorted top-16 ------------------------
__global__ __launch_bounds__(256)
void knn_kernel(const float* __restrict__ xyz, int* __restrict__ knn)
{
    extern __shared__ float sh[];
    float* sx = sh;
    float* sy = sh + NPTS;
    float* sz = sh + 2*NPTS;
    float* sq = sh + 3*NPTS;
    const int b = blockIdx.y;
    const float* xb = xyz + (size_t)b * NPTS * 3;
    for (int p = threadIdx.x; p < NPTS; p += blockDim.x) {
        float x = xb[3*p], y = xb[3*p+1], z = xb[3*p+2];
        sx[p] = x; sy[p] = y; sz[p] = z;
        sq[p] = x*x + y*y + z*z;
    }
    __syncthreads();

    const int warp = threadIdx.x >> 5, lane = threadIdx.x & 31;
    for (int qi = warp; qi < 32; qi += 8) {
        const int qn = blockIdx.x * 32 + qi;
        const float qx = sx[qn], qy = sy[qn], qz = sz[qn], qs = sq[qn];

        float ld = FLT_MAX; int li = 0x7fffffff;
        float thd = FLT_MAX; int thi = 0x7fffffff;

        for (int c0 = 0; c0 < NPTS; c0 += 32) {
            const int c = c0 + lane;
            const float dot = qx*sx[c] + qy*sy[c] + qz*sz[c];
            const float d = (qs + sq[c]) - 2.0f * dot;
            unsigned mask = __ballot_sync(FULLMASK, d < thd || (d == thd && c < thi));
            while (mask) {
                const int src = __ffs(mask) - 1;
                mask &= mask - 1;
                const float cd = __shfl_sync(FULLMASK, d, src);
                const int ci = c0 + src;
                if (cd < thd || (cd == thd && ci < thi)) {
                    const bool lt = (ld < cd) || (ld == cd && li < ci);
                    const int pos = __popc(__ballot_sync(FULLMASK, lt) & 0xFFFFu);
                    const float pd = __shfl_up_sync(FULLMASK, ld, 1);
                    const int pi = __shfl_up_sync(FULLMASK, li, 1);
                    if ((int)lane > pos) { ld = pd; li = pi; }
                    else if ((int)lane == pos) { ld = cd; li = ci; }
                    thd = __shfl_sync(FULLMASK, ld, 15);
                    thi = __shfl_sync(FULLMASK, li, 15);
                } else {
                    __shfl_up_sync(FULLMASK, ld, 1);
                    __shfl_up_sync(FULLMASK, li, 1);
                    __shfl_sync(FULLMASK, ld, 15);
                    __shfl_sync(FULLMASK, li, 15);
                }
            }
        }

        if (lane < 16) knn[((size_t)(b*NPTS + qn)) * KNN + lane] = li;
    }
}

// ---------------- fused neighborhood attention (single pass, prefetch) ------
__global__ __launch_bounds__(256)
void attn_k(const float* __restrict__ qkvg, const float* __restrict__ xyz,
            const int* __restrict__ knn, const float* __restrict__ fd1w,
            const float* __restrict__ fd1b, float* __restrict__ svA)
{
    __shared__ float sw[768];
    __shared__ float sb[256];
    const int tid = threadIdx.x;
    for (int i = tid; i < 768; i += 256) sw[i] = fd1w[i];
    for (int i = tid; i < 256; i += 256) sb[i] = fd1b[i];
    __syncthreads();

    const int lane = tid & 31, warp = tid >> 5;
    const int n = blockIdx.x * 8 + warp;
    const int gbase = n & ~(NPTS - 1);

    const float4* qv = (const float4*)(qkvg + (size_t)n * 1024);
    const float4 q0 = qv[lane],        q1 = qv[32 + lane];
    const float4 gg0 = qv[192 + lane], gg1 = qv[224 + lane];

    const int c0 = lane << 2;
    const float4 w00 = *(const float4*)(sw + c0);
    const float4 w01 = *(const float4*)(sw + 256 + c0);
    const float4 w02 = *(const float4*)(sw + 512 + c0);
    const float4 b0v = *(const float4*)(sb + c0);
    const float4 w10 = *(const float4*)(sw + c0 + 128);
    const float4 w11 = *(const float4*)(sw + 256 + c0 + 128);
    const float4 w12 = *(const float4*)(sw + 512 + c0 + 128);
    const float4 b1v = *(const float4*)(sb + c0 + 128);

    const float px = xyz[(size_t)n*3], py = xyz[(size_t)n*3+1], pz = xyz[(size_t)n*3+2];
    int myidx = 0; float mdx = 0.f, mdy = 0.f, mdz = 0.f;
    if (lane < 16) {
        myidx = knn[(size_t)n * KNN + lane];
        const float* nb = xyz + (size_t)(gbase + myidx) * 3;
        mdx = px - nb[0]; mdy = py - nb[1]; mdz = pz - nb[2];
    }

    float m = -FLT_MAX, s = 0.f;
    float4 sv0 = make_float4(0,0,0,0), sv1 = sv0, A0 = sv0, A1 = sv0;

    int cidx = __shfl_sync(FULLMASK, myidx, 0);
    const float4* cp = (const float4*)(qkvg + (size_t)(gbase + cidx) * 1024);
    float4 ck0 = __ldg(cp + 64 + lane),  ck1 = __ldg(cp + 96 + lane);
    float4 cv0 = __ldg(cp + 128 + lane), cv1 = __ldg(cp + 160 + lane);

    #pragma unroll
    for (int k = 0; k < 16; ++k) {
        float4 nk0, nk1, nv0, nv1;
        if (k < 15) {
            const int nidx = __shfl_sync(FULLMASK, myidx, k + 1);
            const float4* np = (const float4*)(qkvg + (size_t)(gbase + nidx) * 1024);
            nk0 = __ldg(np + 64 + lane);  nk1 = __ldg(np + 96 + lane);
            nv0 = __ldg(np + 128 + lane); nv1 = __ldg(np + 160 + lane);
        }
        const float dx = __shfl_sync(FULLMASK, mdx, k);
        const float dy = __shfl_sync(FULLMASK, mdy, k);
        const float dz = __shfl_sync(FULLMASK, mdz, k);
        float4 h0, h1;
        h0.x = fmaxf(0.f, dx*w00.x + dy*w01.x + dz*w02.x + b0v.x);
        h0.y = fmaxf(0.f, dx*w00.y + dy*w01.y + dz*w02.y + b0v.y);
        h0.z = fmaxf(0.f, dx*w00.z + dy*w01.z + dz*w02.z + b0v.z);
        h0.w = fmaxf(0.f, dx*w00.w + dy*w01.w + dz*w02.w + b0v.w);
        h1.x = fmaxf(0.f, dx*w10.x + dy*w11.x + dz*w12.x + b1v.x);
        h1.y = fmaxf(0.f, dx*w10.y + dy*w11.y + dz*w12.y + b1v.y);
        h1.z = fmaxf(0.f, dx*w10.z + dy*w11.z + dz*w12.z + b1v.z);
        h1.w = fmaxf(0.f, dx*w10.w + dy*w11.w + dz*w12.w + b1v.w);
        float p = q0.x*ck0.x + q0.y*ck0.y + q0.z*ck0.z + q0.w*ck0.w
                + q1.x*ck1.x + q1.y*ck1.y + q1.z*ck1.z + q1.w*ck1.w
                + h0.x*gg0.x + h0.y*gg0.y + h0.z*gg0.z + h0.w*gg0.w
                + h1.x*gg1.x + h1.y*gg1.y + h1.z*gg1.z + h1.w*gg1.w;
        #pragma unroll
        for (int off = 16; off; off >>= 1) p += __shfl_xor_sync(FULLMASK, p, off);
        p *= 0.0625f;

        const float mn = fmaxf(m, p);
        const float corr = __expf(m - mn);
        const float a = __expf(p - mn);
        m = mn;
        s = s * corr + a;
        sv0.x = sv0.x*corr + a*cv0.x; sv0.y = sv0.y*corr + a*cv0.y;
        sv0.z = sv0.z*corr + a*cv0.z; sv0.w = sv0.w*corr + a*cv0.w;
        sv1.x = sv1.x*corr + a*cv1.x; sv1.y = sv1.y*corr + a*cv1.y;
        sv1.z = sv1.z*corr + a*cv1.z; sv1.w = sv1.w*corr + a*cv1.w;
        A0.x = A0.x*corr + a*h0.x; A0.y = A0.y*corr + a*h0.y;
        A0.z = A0.z*corr + a*h0.z; A0.w = A0.w*corr + a*h0.w;
        A1.x = A1.x*corr + a*h1.x; A1.y = A1.y*corr + a*h1.y;
        A1.z = A1.z*corr + a*h1.z; A1.w = A1.w*corr + a*h1.w;
        ck0 = nk0; ck1 = nk1; cv0 = nv0; cv1 = nv1;
    }

    const float inv = 1.f / s;
    sv0.x *= inv; sv0.y *= inv; sv0.z *= inv; sv0.w *= inv;
    sv1.x *= inv; sv1.y *= inv; sv1.z *= inv; sv1.w *= inv;
    A0.x *= inv; A0.y *= inv; A0.z *= inv; A0.w *= inv;
    A1.x *= inv; A1.y *= inv; A1.z *= inv; A1.w *= inv;

    float4* o = (float4*)(svA + (size_t)n * 512);
    o[lane] = sv0; o[32 + lane] = sv1; o[64 + lane] = A0; o[96 + lane] = A1;
}

// ---------------- launch -----------------------------------------------------
extern "C" void kernel_launch(void* const* d_in, const int* in_sizes, int n_in,
                              void* d_out, int out_size)
{
    const float* features = (const float*)d_in[0];
    const float* xyz      = (const float*)d_in[1];
    const float* fc1w     = (const float*)d_in[2];
    const float* fc1b     = (const float*)d_in[3];
    const float* fc2w     = (const float*)d_in[4];
    const float* fc2b     = (const float*)d_in[5];
    const float* fd1w     = (const float*)d_in[6];
    const float* fd1b     = (const float*)d_in[7];
    const float* fd2w     = (const float*)d_in[8];
    const float* fd2b     = (const float*)d_in[9];
    const float* wq       = (const float*)d_in[10];
    const float* wk       = (const float*)d_in[11];
    const float* wv       = (const float*)d_in[12];
    float* out = (float*)d_out;

    void *p_qkvg, *p_svA, *p_knn, *p_W1big, *p_bvec, *p_W2, *p_cvec;
    cudaGetSymbolAddress(&p_qkvg, g_qkvg);
    cudaGetSymbolAddress(&p_svA, g_svA);
    cudaGetSymbolAddress(&p_knn, g_knn);
    cudaGetSymbolAddress(&p_W1big, g_W1big);
    cudaGetSymbolAddress(&p_bvec, g_bvec);
    cudaGetSymbolAddress(&p_W2, g_W2);
    cudaGetSymbolAddress(&p_cvec, g_cvec);
    float* W1big = (float*)p_W1big;
    float* W2 = (float*)p_W2;

    // ---- KNN first (independent of weight prep) ----
    cudaFuncSetAttribute((const void*)knn_kernel,
                         cudaFuncAttributeMaxDynamicSharedMemorySize, 65536);
    knn_kernel<<<dim3(128, BB), 256, 65536>>>(xyz, (int*)p_knn);

    // ---- fused weight prep (2 launches) ----
    prep1_k<<<40, 256>>>(fc1w, wq, wk, wv, fd2w, fc2w, fc1b, fd2b, fc2b,
                         W1big, (float*)p_bvec, W2, (float*)p_cvec);
    prep2_k<<<9, 256>>>(fd2w, W1big, (float*)p_bvec);

    // ---- [q|k|v|g] = features @ W1big + bvec  (tf32 tensor cores) ----
    tf32gemm_k<0><<<dim3(8, 128), 256, 35840>>>(
        features, W1big, (const float*)p_bvec, (float*)p_qkvg,
        TOT, 1024, 128, nullptr);

    // ---- attention -> [sv|A] ----
    attn_k<<<2048, 256>>>((const float*)p_qkvg, xyz, (const int*)p_knn,
                          fd1w, fd1b, (float*)p_svA);

    // ---- out = [sv|A] @ W2 + cvec + features (tf32), transposed store ----
    cudaFuncSetAttribute((const void*)tf32gemm_k<1>,
                         cudaFuncAttributeMaxDynamicSharedMemorySize, 67584);
    tf32gemm_k<1><<<dim3(1, 128), 256, 67584>>>(
        (const float*)p_svA, W2, (const float*)p_cvec, out,
        TOT, 128, 512, features);
}